// round 9
// baseline (speedup 1.0000x reference)
#include <cuda_runtime.h>
#include <math.h>

// Problem constants (validated against in_sizes at launch time)
#define NN 100000
#define NE 1600000
#define NF 64
#define NG 256

// ---------------- device scratch (static; no allocations) ----------------
__device__ int    g_anyodd_v9;             // dtype probe: nonzero odd word seen
__device__ int    g_degi_v9[NN];           // degree incl. self loop
__device__ float  g_dinv_v9[NN];           // rsqrt(deg)
__device__ int    g_rp_v9[NN + 1];         // CSR row pointers (real edges only)
__device__ int    g_rpl_v9[NN];            // per-chunk local exclusive scan
__device__ int    g_cursor_v9[NN];         // fill cursors
__device__ int    g_partials_v9[512];      // block partial sums for scan
__device__ int    g_col_v9[NE];            // CSR column (src) indices
__device__ float2 g_bufA_v9[NN * 32];      // tmp = (X@W)*dinv  (gemm out / agg in)
__device__ float2 g_bufB_v9[NN * 32];      // h after aggregation+relu (agg out)
__device__ float  g_sums_v9[NG * 64];      // pooled sums
__device__ int    g_cnt_v9[NG];            // nodes per graph

// dtype-agnostic index load: int64 buffers have zero odd (high) words.
__device__ __forceinline__ int ld_idx(const void* p, int i, int is64) {
    if (is64) return (int)((const long long*)p)[i];
    return ((const int*)p)[i];
}
__device__ __forceinline__ int clampi(int v, int hi) {   // [0, hi]
    return v < 0 ? 0 : (v > hi ? hi : v);
}

// ---------------- kernels ----------------

__global__ void init_v9(int n) {
    int i = blockIdx.x * blockDim.x + threadIdx.x;
    if (i == 0) g_anyodd_v9 = 0;
    if (i < n) g_degi_v9[i] = 1;           // self loop contributes 1
    if (i < NG * 64) g_sums_v9[i] = 0.0f;
    if (i < NG) g_cnt_v9[i] = 0;
}

// Probe: any nonzero odd 32-bit word in the first 4096 words => int32 data.
__global__ void detect_v9(const int* ei_words, int nwords) {
    int i = blockIdx.x * blockDim.x + threadIdx.x;
    int idx = 2 * i + 1;
    if (idx < nwords && ei_words[idx] != 0) atomicOr(&g_anyodd_v9, 1);
}

__global__ void count_v9(const void* ei, int E, int n) {
    int e = blockIdx.x * blockDim.x + threadIdx.x;
    if (e >= E) return;
    int is64 = (g_anyodd_v9 == 0);
    int d = clampi(ld_idx(ei, E + e, is64), n - 1);
    atomicAdd(&g_degi_v9[d], 1);
}

// Exclusive scan of (deg-1) per 512-node chunk, shuffle-based.
__global__ void scan1_v9(int n) {
    __shared__ int wtot[17];
    int t = threadIdx.x;
    int i = blockIdx.x * 512 + t;
    int lane = t & 31;
    int w = t >> 5;

    if (t < 17) wtot[t] = 0;
    __syncthreads();

    int v = (i < n) ? (g_degi_v9[i] - 1) : 0;
    int s = v;
    #pragma unroll
    for (int off = 1; off < 32; off <<= 1) {
        int y = __shfl_up_sync(0xffffffffu, s, off);
        if (lane >= off) s += y;
    }
    if (lane == 31) wtot[w + 1] = s;
    __syncthreads();

    if (t == 0) {
        int acc = 0;
        #pragma unroll
        for (int k = 1; k <= 16; k++) { acc += wtot[k]; wtot[k] = acc; }
    }
    __syncthreads();

    if (i < n) g_rpl_v9[i] = wtot[w] + (s - v);
    if (t == 511) g_partials_v9[blockIdx.x] = wtot[15] + s;   // block total
}

__global__ void scan2_v9(int nb) {
    __shared__ int wtot[17];
    int t = threadIdx.x;
    int lane = t & 31;
    int w = t >> 5;

    if (t < 17) wtot[t] = 0;
    __syncthreads();

    int v = (t < nb) ? g_partials_v9[t] : 0;
    int s = v;
    #pragma unroll
    for (int off = 1; off < 32; off <<= 1) {
        int y = __shfl_up_sync(0xffffffffu, s, off);
        if (lane >= off) s += y;
    }
    if (lane == 31) wtot[w + 1] = s;
    __syncthreads();

    if (t == 0) {
        int acc = 0;
        #pragma unroll
        for (int k = 1; k <= 16; k++) { acc += wtot[k]; wtot[k] = acc; }
    }
    __syncthreads();

    if (t < nb) g_partials_v9[t] = wtot[w] + (s - v);
}

__global__ void scan3_v9(int n, int E) {
    int i = blockIdx.x * 512 + threadIdx.x;
    if (i < n) {
        int v = g_rpl_v9[i] + g_partials_v9[i >> 9];
        g_rp_v9[i] = v;
        g_cursor_v9[i] = v;
        g_dinv_v9[i] = rsqrtf((float)g_degi_v9[i]);
    }
    if (i == 0) g_rp_v9[n] = E;
}

__global__ void fill_v9(const void* ei, int E, int n) {
    int e = blockIdx.x * blockDim.x + threadIdx.x;
    if (e >= E) return;
    int is64 = (g_anyodd_v9 == 0);
    int s = clampi(ld_idx(ei, e, is64), n - 1);
    int d = clampi(ld_idx(ei, E + e, is64), n - 1);
    int pos = atomicAdd(&g_cursor_v9[d], 1);   // in [rp[d], rp[d+1]) by construction
    g_col_v9[pos] = s;
}

// g_bufA[i,:] = (X[i,:] @ W) * dinv[i].  X = input if use_ext else g_bufB.
// One row per warp; W resident in smem as float2.
__global__ void gemm_v9(const float* __restrict__ Xext, int use_ext,
                        const float* __restrict__ W, int n) {
    __shared__ float2 Ws[64 * 32];   // Ws[k*32+l] = {W[k][2l], W[k][2l+1]}
    for (int i = threadIdx.x; i < 64 * 32; i += blockDim.x)
        Ws[i] = ((const float2*)W)[i];
    __syncthreads();

    const float* X = use_ext ? Xext : (const float*)g_bufB_v9;

    int lane = threadIdx.x & 31;
    int row = (blockIdx.x * blockDim.x + threadIdx.x) >> 5;
    if (row >= n) return;

    const float* xr = X + row * 64;
    float ax = 0.f, ay = 0.f;
    #pragma unroll
    for (int k = 0; k < 64; k++) {
        float xv = xr[k];                  // broadcast load
        float2 w = Ws[k * 32 + lane];
        ax = fmaf(xv, w.x, ax);
        ay = fmaf(xv, w.y, ay);
    }
    float dv = g_dinv_v9[row];
    g_bufA_v9[row * 32 + lane] = make_float2(ax * dv, ay * dv);
}

// g_bufB[d,:] = relu( dinv[d] * (tmp[d,:] + sum_{s in N(d)} tmp[s,:]) + b )
// One warp per node, float2 per lane, 2-deep edge unroll.
__global__ void agg_v9(const float* __restrict__ bias, int n) {
    int node = (blockIdx.x * blockDim.x + threadIdx.x) >> 5;
    int lane = threadIdx.x & 31;
    if (node >= n) return;

    int beg = g_rp_v9[node];
    int end = g_rp_v9[node + 1];

    float2 self = g_bufA_v9[node * 32 + lane];
    float a0x = self.x, a0y = self.y;
    float a1x = 0.f,    a1y = 0.f;

    int e = beg;
    for (; e + 1 < end; e += 2) {
        int c0 = g_col_v9[e];
        int c1 = g_col_v9[e + 1];
        float2 v0 = g_bufA_v9[c0 * 32 + lane];
        float2 v1 = g_bufA_v9[c1 * 32 + lane];
        a0x += v0.x; a0y += v0.y;
        a1x += v1.x; a1y += v1.y;
    }
    if (e < end) {
        int c = g_col_v9[e];
        float2 v = g_bufA_v9[c * 32 + lane];
        a0x += v.x; a0y += v.y;
    }

    float dv = g_dinv_v9[node];
    float bx = bias[2 * lane];
    float by = bias[2 * lane + 1];
    g_bufB_v9[node * 32 + lane] =
        make_float2(fmaxf(fmaf(dv, a0x + a1x, bx), 0.f),
                    fmaxf(fmaf(dv, a0y + a1y, by), 0.f));
}

// sorted-batch segment-sum with local run accumulation over g_bufB.
#define PNODES 512
__global__ void pool_v9(const void* batch, int n) {
    int base = blockIdx.x * PNODES;
    int l  = threadIdx.x & 31;            // float2 lane (features 2l, 2l+1)
    int rg = threadIdx.x >> 5;            // 0..7
    int is64 = (g_anyodd_v9 == 0);
    float ax = 0.f, ay = 0.f;
    int cur = -1, cnt = 0;
    for (int i = rg; i < PNODES; i += 8) {
        int node = base + i;
        if (node >= n) break;
        int g = clampi(ld_idx(batch, node, is64), NG - 1);
        if (g != cur) {
            if (cur >= 0) {
                atomicAdd(&g_sums_v9[cur * 64 + 2 * l], ax);
                atomicAdd(&g_sums_v9[cur * 64 + 2 * l + 1], ay);
                if (l == 0) atomicAdd(&g_cnt_v9[cur], cnt);
            }
            cur = g; ax = 0.f; ay = 0.f; cnt = 0;
        }
        float2 v = g_bufB_v9[node * 32 + l];
        ax += v.x; ay += v.y;
        cnt++;
    }
    if (cur >= 0) {
        atomicAdd(&g_sums_v9[cur * 64 + 2 * l], ax);
        atomicAdd(&g_sums_v9[cur * 64 + 2 * l + 1], ay);
        if (l == 0) atomicAdd(&g_cnt_v9[cur], cnt);
    }
}

__global__ void head_v9(const float* __restrict__ Wfc,
                        const float* __restrict__ bfc,
                        float* __restrict__ out) {
    int g = blockIdx.x * blockDim.x + threadIdx.x;
    if (g >= NG) return;
    float acc = 0.f;
    #pragma unroll
    for (int j = 0; j < 64; j++)
        acc = fmaf(g_sums_v9[g * 64 + j], Wfc[j], acc);
    float c = (float)g_cnt_v9[g];
    if (c < 1.0f) c = 1.0f;
    float z = acc / c + bfc[0];
    out[g] = 1.0f / (1.0f + expf(-z));
}

// ---------------- launch (kernel launches only; graph-capturable) ----------------
extern "C" void kernel_launch(void* const* d_in, const int* in_sizes, int n_in,
                              void* d_out, int out_size) {
    const float* x     = (const float*)d_in[0];
    const void*  ei    = d_in[1];
    const void*  batch = d_in[2];
    const float* W1    = (const float*)d_in[3];
    const float* b1    = (const float*)d_in[4];
    const float* W2    = (const float*)d_in[5];
    const float* b2    = (const float*)d_in[6];
    const float* Wfc   = (const float*)d_in[7];
    const float* bfc   = (const float*)d_in[8];
    float* out = (float*)d_out;

    int N = in_sizes[0] / NF;              // 100000
    int E = in_sizes[1] / 2;               // 1600000 (element count, dtype-independent)
    if (N > NN) N = NN;
    if (E > NE) E = NE;

    int nScan  = (N + 511) / 512;          // 196
    int bEdge  = (E + 255) / 256;
    int bNode  = (N + 255) / 256;
    int bWarp  = (N + 7) / 8;              // warp-per-node, 8 warps/block

    // dtype probe samples the first 4096 int32 words (safe for either dtype:
    // buffer holds 2E logical elements >= 4096 words in both layouts).
    init_v9<<<bNode, 256>>>(N);
    detect_v9<<<8, 256>>>((const int*)ei, 4096);

    // --- graph structure ---
    count_v9<<<bEdge, 256>>>(ei, E, N);
    scan1_v9<<<nScan, 512>>>(N);
    scan2_v9<<<1, 512>>>(nScan);
    scan3_v9<<<nScan, 512>>>(N, E);
    fill_v9<<<bEdge, 256>>>(ei, E, N);

    // --- layer 1: x -> bufA -> bufB ---
    gemm_v9<<<bWarp, 256>>>(x, 1, W1, N);
    agg_v9<<<bWarp, 256>>>(b1, N);

    // --- layer 2: bufB -> bufA -> bufB ---
    gemm_v9<<<bWarp, 256>>>(x, 0, W2, N);
    agg_v9<<<bWarp, 256>>>(b2, N);

    // --- pooling + head ---
    pool_v9<<<(N + PNODES - 1) / PNODES, 256>>>(batch, N);
    head_v9<<<1, 256>>>(Wfc, bfc, out);
}

// round 10
// speedup vs baseline: 1.0144x; 1.0144x over previous
#include <cuda_runtime.h>
#include <math.h>

// Problem constants (validated against in_sizes at launch time)
#define NN 100000
#define NE 1600000
#define NF 64
#define NG 256

// ---------------- device scratch (static; no allocations) ----------------
__device__ int    g_anyodd_v10;             // dtype probe: nonzero odd word seen
__device__ int    g_degi_v10[NN];           // degree incl. self loop
__device__ float  g_dinv_v10[NN];           // rsqrt(deg)
__device__ int    g_rp_v10[NN + 1];         // CSR row pointers (real edges only)
__device__ int    g_rpl_v10[NN];            // per-chunk local exclusive scan
__device__ int    g_cursor_v10[NN];         // fill cursors
__device__ int    g_partials_v10[512];      // block partial sums for scan
__device__ int    g_col_v10[NE];            // CSR column (src) indices
__device__ float4 g_bufA_v10[NN * 16];      // tmp = (X@W)*dinv  (row = 16 float4)
__device__ float4 g_bufB_v10[NN * 16];      // h after aggregation+relu
__device__ float  g_sums_v10[NG * 64];      // pooled sums
__device__ int    g_cnt_v10[NG];            // nodes per graph

// dtype-agnostic index load: int64 buffers have zero odd (high) words.
__device__ __forceinline__ int ld_idx(const void* p, int i, int is64) {
    if (is64) return (int)((const long long*)p)[i];
    return ((const int*)p)[i];
}
__device__ __forceinline__ int clampi(int v, int hi) {
    return v < 0 ? 0 : (v > hi ? hi : v);
}

// ---------------- kernels ----------------

// init scratch + dtype probe (any nonzero odd 32-bit word => int32 data)
__global__ void initdet_v10(const int* ei_words, int n) {
    int i = blockIdx.x * blockDim.x + threadIdx.x;
    if (i == 0) g_anyodd_v10 = 0;
    if (i < n) g_degi_v10[i] = 1;            // self loop contributes 1
    if (i < NG * 64) g_sums_v10[i] = 0.0f;
    if (i < NG) g_cnt_v10[i] = 0;
    if (i < 2048 && ei_words[2 * i + 1] != 0) atomicOr(&g_anyodd_v10, 1);
}

__global__ void count_v10(const void* ei, int E, int n) {
    int e = blockIdx.x * blockDim.x + threadIdx.x;
    if (e >= E) return;
    int is64 = (g_anyodd_v10 == 0);
    int d = clampi(ld_idx(ei, E + e, is64), n - 1);
    atomicAdd(&g_degi_v10[d], 1);
}

// Exclusive scan of (deg-1) per 512-node chunk, shuffle-based.
__global__ void scan1_v10(int n) {
    __shared__ int wtot[17];
    int t = threadIdx.x;
    int i = blockIdx.x * 512 + t;
    int lane = t & 31;
    int w = t >> 5;

    if (t < 17) wtot[t] = 0;
    __syncthreads();

    int v = (i < n) ? (g_degi_v10[i] - 1) : 0;
    int s = v;
    #pragma unroll
    for (int off = 1; off < 32; off <<= 1) {
        int y = __shfl_up_sync(0xffffffffu, s, off);
        if (lane >= off) s += y;
    }
    if (lane == 31) wtot[w + 1] = s;
    __syncthreads();

    if (t == 0) {
        int acc = 0;
        #pragma unroll
        for (int k = 1; k <= 16; k++) { acc += wtot[k]; wtot[k] = acc; }
    }
    __syncthreads();

    if (i < n) g_rpl_v10[i] = wtot[w] + (s - v);
    if (t == 511) g_partials_v10[blockIdx.x] = wtot[15] + s;   // block total
}

__global__ void scan2_v10(int nb) {
    __shared__ int wtot[17];
    int t = threadIdx.x;
    int lane = t & 31;
    int w = t >> 5;

    if (t < 17) wtot[t] = 0;
    __syncthreads();

    int v = (t < nb) ? g_partials_v10[t] : 0;
    int s = v;
    #pragma unroll
    for (int off = 1; off < 32; off <<= 1) {
        int y = __shfl_up_sync(0xffffffffu, s, off);
        if (lane >= off) s += y;
    }
    if (lane == 31) wtot[w + 1] = s;
    __syncthreads();

    if (t == 0) {
        int acc = 0;
        #pragma unroll
        for (int k = 1; k <= 16; k++) { acc += wtot[k]; wtot[k] = acc; }
    }
    __syncthreads();

    if (t < nb) g_partials_v10[t] = wtot[w] + (s - v);
}

__global__ void scan3_v10(int n, int E) {
    int i = blockIdx.x * 512 + threadIdx.x;
    if (i < n) {
        int v = g_rpl_v10[i] + g_partials_v10[i >> 9];
        g_rp_v10[i] = v;
        g_cursor_v10[i] = v;
        g_dinv_v10[i] = rsqrtf((float)g_degi_v10[i]);
    }
    if (i == 0) g_rp_v10[n] = E;
}

__global__ void fill_v10(const void* ei, int E, int n) {
    int e = blockIdx.x * blockDim.x + threadIdx.x;
    if (e >= E) return;
    int is64 = (g_anyodd_v10 == 0);
    int s = clampi(ld_idx(ei, e, is64), n - 1);
    int d = clampi(ld_idx(ei, E + e, is64), n - 1);
    int pos = atomicAdd(&g_cursor_v10[d], 1);  // in [rp[d], rp[d+1]) by construction
    g_col_v10[pos] = s;
}

// g_bufA[i,:] = (X[i,:] @ W) * dinv[i].  X = input if use_ext else g_bufB.
// One row per warp; W resident in smem as float2.
__global__ void gemm_v10(const float* __restrict__ Xext, int use_ext,
                         const float* __restrict__ W, int n) {
    __shared__ float2 Ws[64 * 32];   // Ws[k*32+l] = {W[k][2l], W[k][2l+1]}
    for (int i = threadIdx.x; i < 64 * 32; i += blockDim.x)
        Ws[i] = ((const float2*)W)[i];
    __syncthreads();

    const float* X = use_ext ? Xext : (const float*)g_bufB_v10;

    int lane = threadIdx.x & 31;
    int row = (blockIdx.x * blockDim.x + threadIdx.x) >> 5;
    if (row >= n) return;

    const float* xr = X + row * 64;
    float ax = 0.f, ay = 0.f;
    #pragma unroll
    for (int k = 0; k < 64; k++) {
        float xv = xr[k];                  // broadcast load
        float2 w = Ws[k * 32 + lane];
        ax = fmaf(xv, w.x, ax);
        ay = fmaf(xv, w.y, ay);
    }
    float dv = g_dinv_v10[row];
    ((float2*)g_bufA_v10)[row * 32 + lane] = make_float2(ax * dv, ay * dv);
}

// g_bufB[d,:] = relu( dinv[d] * (tmp[d,:] + sum_{s in N(d)} tmp[s,:]) + b )
// Warp = node. Lanes 0-15 handle even edges, 16-31 odd edges; each lane
// gathers one float4 chunk (16B) of the 256B neighbor row -> 1 LDG.128 per
// 2 edges. Halves combined with shfl.xor(16).
__global__ void agg_v10(const float* __restrict__ bias, int n) {
    int node = (blockIdx.x * blockDim.x + threadIdx.x) >> 5;
    int lane = threadIdx.x & 31;
    if (node >= n) return;

    int half = lane >> 4;       // 0: even edges, 1: odd edges
    int c    = lane & 15;       // float4 chunk within row

    int beg = g_rp_v10[node];
    int end = g_rp_v10[node + 1];

    float4 acc;
    if (half == 0) {
        acc = g_bufA_v10[node * 16 + c];     // self-loop term (pre-scaled)
    } else {
        acc = make_float4(0.f, 0.f, 0.f, 0.f);
    }

    for (int e = beg + half; e < end; e += 2) {
        int col = g_col_v10[e];
        float4 v = g_bufA_v10[col * 16 + c];
        acc.x += v.x; acc.y += v.y; acc.z += v.z; acc.w += v.w;
    }

    // combine odd/even halves (chunk c lives in lanes c and c+16)
    acc.x += __shfl_xor_sync(0xffffffffu, acc.x, 16);
    acc.y += __shfl_xor_sync(0xffffffffu, acc.y, 16);
    acc.z += __shfl_xor_sync(0xffffffffu, acc.z, 16);
    acc.w += __shfl_xor_sync(0xffffffffu, acc.w, 16);

    if (half == 0) {
        float dv = g_dinv_v10[node];
        float4 bb = ((const float4*)bias)[c];
        float4 o;
        o.x = fmaxf(fmaf(dv, acc.x, bb.x), 0.f);
        o.y = fmaxf(fmaf(dv, acc.y, bb.y), 0.f);
        o.z = fmaxf(fmaf(dv, acc.z, bb.z), 0.f);
        o.w = fmaxf(fmaf(dv, acc.w, bb.w), 0.f);
        g_bufB_v10[node * 16 + c] = o;
    }
}

// sorted-batch segment-sum with local run accumulation over g_bufB.
#define PNODES 512
__global__ void pool_v10(const void* batch, int n) {
    int base = blockIdx.x * PNODES;
    int l  = threadIdx.x & 31;            // float2 lane (features 2l, 2l+1)
    int rg = threadIdx.x >> 5;            // 0..7
    int is64 = (g_anyodd_v10 == 0);
    const float2* B2 = (const float2*)g_bufB_v10;
    float ax = 0.f, ay = 0.f;
    int cur = -1, cnt = 0;
    for (int i = rg; i < PNODES; i += 8) {
        int node = base + i;
        if (node >= n) break;
        int g = clampi(ld_idx(batch, node, is64), NG - 1);
        if (g != cur) {
            if (cur >= 0) {
                atomicAdd(&g_sums_v10[cur * 64 + 2 * l], ax);
                atomicAdd(&g_sums_v10[cur * 64 + 2 * l + 1], ay);
                if (l == 0) atomicAdd(&g_cnt_v10[cur], cnt);
            }
            cur = g; ax = 0.f; ay = 0.f; cnt = 0;
        }
        float2 v = B2[node * 32 + l];
        ax += v.x; ay += v.y;
        cnt++;
    }
    if (cur >= 0) {
        atomicAdd(&g_sums_v10[cur * 64 + 2 * l], ax);
        atomicAdd(&g_sums_v10[cur * 64 + 2 * l + 1], ay);
        if (l == 0) atomicAdd(&g_cnt_v10[cur], cnt);
    }
}

__global__ void head_v10(const float* __restrict__ Wfc,
                         const float* __restrict__ bfc,
                         float* __restrict__ out) {
    int g = blockIdx.x * blockDim.x + threadIdx.x;
    if (g >= NG) return;
    float acc = 0.f;
    #pragma unroll
    for (int j = 0; j < 64; j++)
        acc = fmaf(g_sums_v10[g * 64 + j], Wfc[j], acc);
    float c = (float)g_cnt_v10[g];
    if (c < 1.0f) c = 1.0f;
    float z = acc / c + bfc[0];
    out[g] = 1.0f / (1.0f + expf(-z));
}

// ---------------- launch (kernel launches only; graph-capturable) ----------------
extern "C" void kernel_launch(void* const* d_in, const int* in_sizes, int n_in,
                              void* d_out, int out_size) {
    const float* x     = (const float*)d_in[0];
    const void*  ei    = d_in[1];
    const void*  batch = d_in[2];
    const float* W1    = (const float*)d_in[3];
    const float* b1    = (const float*)d_in[4];
    const float* W2    = (const float*)d_in[5];
    const float* b2    = (const float*)d_in[6];
    const float* Wfc   = (const float*)d_in[7];
    const float* bfc   = (const float*)d_in[8];
    float* out = (float*)d_out;

    int N = in_sizes[0] / NF;              // 100000
    int E = in_sizes[1] / 2;               // 1600000 (element count, dtype-independent)
    if (N > NN) N = NN;
    if (E > NE) E = NE;

    int nScan = (N + 511) / 512;           // 196
    int bEdge = (E + 255) / 256;
    int bNode = (N + 255) / 256;
    int bWarp = (N + 7) / 8;               // warp-per-node, 8 warps/block

    // --- init + dtype probe + graph structure ---
    initdet_v10<<<bNode, 256>>>((const int*)ei, N);
    count_v10<<<bEdge, 256>>>(ei, E, N);
    scan1_v10<<<nScan, 512>>>(N);
    scan2_v10<<<1, 512>>>(nScan);
    scan3_v10<<<nScan, 512>>>(N, E);
    fill_v10<<<bEdge, 256>>>(ei, E, N);

    // --- layer 1: x -> bufA -> bufB ---
    gemm_v10<<<bWarp, 256>>>(x, 1, W1, N);
    agg_v10<<<bWarp, 256>>>(b1, N);

    // --- layer 2: bufB -> bufA -> bufB ---
    gemm_v10<<<bWarp, 256>>>(x, 0, W2, N);
    agg_v10<<<bWarp, 256>>>(b2, N);

    // --- pooling + head ---
    pool_v10<<<(N + PNODES - 1) / PNODES, 256>>>(batch, N);
    head_v10<<<1, 256>>>(Wfc, bfc, out);
}